// round 1
// baseline (speedup 1.0000x reference)
#include <cuda_runtime.h>

// Problem constants
// B=4, T=1024, C=1024, H=16, D=64, BH = B*H = 64
#define NT 1024
#define NC 1024

// ---------------- scratch (no allocations allowed) ----------------
__device__ float g_q   [64 * 1024 * 64];        // [BH][T][D]
__device__ float g_kT  [64 * 64 * 1024];        // [BH][D][T]  (K pre-transposed)
__device__ float g_v   [64 * 1024 * 64];        // [BH][T][D]
__device__ float g_s   [64 * 1024 * 1024];      // [BH][T][T] scores / probs (256 MB)
__device__ float g_attn[4 * 1024 * 1024];       // [B,T,C]
__device__ float g_proj[4 * 1024 * 1024];       // [B,T,C]

// =====================================================================
// Kernel 1: fused QKV projection.  out = x @ W + b, scattered to head
// layout.  128x128x8 fp32 sgemm, blockIdx.z selects {Q,K,V}.
// K is written transposed to [BH][D][T] so the scores kernel loads it
// directly in d-major layout (no smem transpose later).
// =====================================================================
__global__ __launch_bounds__(256) void qkv_kernel(
    const float* __restrict__ x,
    const float* __restrict__ Wq, const float* __restrict__ bq,
    const float* __restrict__ Wk, const float* __restrict__ bk,
    const float* __restrict__ Wv, const float* __restrict__ bv)
{
    __shared__ float As[8][128];
    __shared__ float Bs[8][128];

    const int z = blockIdx.z;
    const float* __restrict__ W    = (z == 0) ? Wq : (z == 1) ? Wk : Wv;
    const float* __restrict__ bias = (z == 0) ? bq : (z == 1) ? bk : bv;

    const int tid = threadIdx.x;
    const int bm = blockIdx.y * 128;
    const int bn = blockIdx.x * 128;

    const int arow = tid >> 1;            // 0..127
    const int acol = (tid & 1) * 4;       // 0 or 4
    const int brow = tid >> 5;            // 0..7
    const int bcol = (tid & 31) * 4;      // 0..124

    const float* Ap = x + (size_t)(bm + arow) * NC + acol;
    const float* Bp = W + (size_t)brow * NC + bn + bcol;

    float acc[8][8];
    #pragma unroll
    for (int i = 0; i < 8; i++)
        #pragma unroll
        for (int j = 0; j < 8; j++) acc[i][j] = 0.f;

    const int tx = tid & 15, ty = tid >> 4;

    for (int k0 = 0; k0 < NC; k0 += 8) {
        float4 av  = *(const float4*)(Ap + k0);
        float4 bv4 = *(const float4*)(Bp + (size_t)k0 * NC);
        As[acol + 0][arow] = av.x;
        As[acol + 1][arow] = av.y;
        As[acol + 2][arow] = av.z;
        As[acol + 3][arow] = av.w;
        *(float4*)&Bs[brow][bcol] = bv4;
        __syncthreads();
        #pragma unroll
        for (int k = 0; k < 8; k++) {
            float a[8], b[8];
            *(float4*)&a[0] = *(const float4*)&As[k][ty * 4];
            *(float4*)&a[4] = *(const float4*)&As[k][64 + ty * 4];
            *(float4*)&b[0] = *(const float4*)&Bs[k][tx * 4];
            *(float4*)&b[4] = *(const float4*)&Bs[k][64 + tx * 4];
            #pragma unroll
            for (int i = 0; i < 8; i++)
                #pragma unroll
                for (int j = 0; j < 8; j++)
                    acc[i][j] = fmaf(a[i], b[j], acc[i][j]);
        }
        __syncthreads();
    }

    float bj[8];
    #pragma unroll
    for (int j = 0; j < 8; j++) {
        int n = bn + ((j < 4) ? tx * 4 + j : 64 + tx * 4 + j - 4);
        bj[j] = bias[n];
    }
    #pragma unroll
    for (int i = 0; i < 8; i++) {
        int m = bm + ((i < 4) ? ty * 4 + i : 64 + ty * 4 + i - 4);
        int bb = m >> 10;          // batch
        int t  = m & 1023;         // token
        #pragma unroll
        for (int j = 0; j < 8; j++) {
            int n = bn + ((j < 4) ? tx * 4 + j : 64 + tx * 4 + j - 4);
            int h = n >> 6, d = n & 63;
            int bh = bb * 16 + h;
            float val = acc[i][j] + bj[j];
            if (z == 0)      g_q [((size_t)bh * NT + t) * 64 + d]  = val;
            else if (z == 1) g_kT[((size_t)bh * 64 + d) * NT + t]  = val;
            else             g_v [((size_t)bh * NT + t) * 64 + d]  = val;
        }
    }
}

// =====================================================================
// Kernel 2: scores.  S[bh, q, k] = scale * sum_d Q[bh,q,d] * K[bh,k,d]
// One block: 128 q-rows x 128 k-cols, full D=64 in one shot.
// Dynamic smem: Qs[128][68] row-major (padded), Ks[64][132] d-major.
// =====================================================================
__global__ __launch_bounds__(256) void scores_kernel()
{
    extern __shared__ float sm[];
    float* Qs = sm;                 // [128][68]
    float* Ks = sm + 128 * 68;      // [64][132]

    const int bh = blockIdx.z;
    const int bq = blockIdx.y * 128;
    const int bk = blockIdx.x * 128;
    const int tid = threadIdx.x;

    const float* qptr = g_q  + ((size_t)bh * NT + bq) * 64;
    const float* kptr = g_kT + (size_t)bh * 64 * NT + bk;

    // Q tile: 128x64 = 2048 float4, direct row-major copy
    #pragma unroll
    for (int i = tid; i < 2048; i += 256) {
        int r = i >> 4, d4 = i & 15;
        *(float4*)&Qs[r * 68 + d4 * 4] = *(const float4*)(qptr + r * 64 + d4 * 4);
    }
    // K tile: 64 d-rows x 128 keys, direct copy from transposed K
    #pragma unroll
    for (int i = tid; i < 2048; i += 256) {
        int d = i >> 5, c4 = i & 31;
        *(float4*)&Ks[d * 132 + c4 * 4] = *(const float4*)(kptr + (size_t)d * NT + c4 * 4);
    }
    __syncthreads();

    const int tx = tid & 15, ty = tid >> 4;
    float acc[8][8];
    #pragma unroll
    for (int i = 0; i < 8; i++)
        #pragma unroll
        for (int j = 0; j < 8; j++) acc[i][j] = 0.f;

    #pragma unroll 8
    for (int d = 0; d < 64; d++) {
        float a[8], b[8];
        #pragma unroll
        for (int i = 0; i < 4; i++) {
            a[i]     = Qs[(ty * 4 + i) * 68 + d];
            a[i + 4] = Qs[(64 + ty * 4 + i) * 68 + d];
        }
        *(float4*)&b[0] = *(const float4*)&Ks[d * 132 + tx * 4];
        *(float4*)&b[4] = *(const float4*)&Ks[d * 132 + 64 + tx * 4];
        #pragma unroll
        for (int i = 0; i < 8; i++)
            #pragma unroll
            for (int j = 0; j < 8; j++)
                acc[i][j] = fmaf(a[i], b[j], acc[i][j]);
    }

    const float scale = 0.125f;   // 1/sqrt(64)
    size_t base = ((size_t)bh * NT + bq) * NT + bk;
    #pragma unroll
    for (int i = 0; i < 8; i++) {
        int r = (i < 4) ? ty * 4 + i : 64 + ty * 4 + i - 4;
        #pragma unroll
        for (int j = 0; j < 8; j++) {
            int col = (j < 4) ? tx * 4 + j : 64 + tx * 4 + j - 4;
            g_s[base + (size_t)r * NT + col] = acc[i][j] * scale;
        }
    }
}

// =====================================================================
// Kernel 3: mask + softmax over each score row (in place).
// grid (T, BH), 256 threads, 4 elems/thread via float4.
// =====================================================================
__global__ __launch_bounds__(256) void softmax_kernel(const int* __restrict__ mask)
{
    __shared__ float red[8];
    const int tid = threadIdx.x;
    float* p = g_s + ((size_t)blockIdx.y * NT + blockIdx.x) * NT;
    const int* m = mask + (blockIdx.y >> 4) * NT;   // batch = bh/16

    float4 v = ((const float4*)p)[tid];
    int4  mk = ((const int4*)m)[tid];
    if (mk.x == 0) v.x = -1e30f;
    if (mk.y == 0) v.y = -1e30f;
    if (mk.z == 0) v.z = -1e30f;
    if (mk.w == 0) v.w = -1e30f;

    float mx = fmaxf(fmaxf(v.x, v.y), fmaxf(v.z, v.w));
    #pragma unroll
    for (int o = 16; o > 0; o >>= 1) mx = fmaxf(mx, __shfl_xor_sync(0xffffffffu, mx, o));
    if ((tid & 31) == 0) red[tid >> 5] = mx;
    __syncthreads();
    float bmx = red[0];
    #pragma unroll
    for (int w = 1; w < 8; w++) bmx = fmaxf(bmx, red[w]);
    __syncthreads();

    v.x = __expf(v.x - bmx);
    v.y = __expf(v.y - bmx);
    v.z = __expf(v.z - bmx);
    v.w = __expf(v.w - bmx);
    float s = v.x + v.y + v.z + v.w;
    #pragma unroll
    for (int o = 16; o > 0; o >>= 1) s += __shfl_xor_sync(0xffffffffu, s, o);
    if ((tid & 31) == 0) red[tid >> 5] = s;
    __syncthreads();
    float tot = 0.f;
    #pragma unroll
    for (int w = 0; w < 8; w++) tot += red[w];

    float inv = 1.0f / tot;
    v.x *= inv; v.y *= inv; v.z *= inv; v.w *= inv;
    ((float4*)p)[tid] = v;
}

// =====================================================================
// Kernel 4: O = P @ V per head.  128 q-rows x 64 cols, BK=32.
// Output written directly in [B,T,C] layout (merged heads).
// =====================================================================
__global__ __launch_bounds__(256) void attnout_kernel()
{
    __shared__ float Ps[128 * 36];   // row-major, padded stride 36
    __shared__ float Vs[32 * 64];    // [kk][n]

    const int bh = blockIdx.y;
    const int bq = blockIdx.x * 128;
    const int tid = threadIdx.x;
    const int tx = tid & 15, ty = tid >> 4;

    const float* srow  = g_s + ((size_t)bh * NT + bq) * NT;
    const float* vbase = g_v + (size_t)bh * NT * 64;

    float acc[8][4];
    #pragma unroll
    for (int i = 0; i < 8; i++)
        #pragma unroll
        for (int j = 0; j < 4; j++) acc[i][j] = 0.f;

    for (int k0 = 0; k0 < NT; k0 += 32) {
        #pragma unroll
        for (int i = tid; i < 1024; i += 256) {
            int r = i >> 3, c4 = i & 7;
            *(float4*)&Ps[r * 36 + c4 * 4] =
                *(const float4*)(srow + (size_t)r * NT + k0 + c4 * 4);
        }
        const float4* vsrc = (const float4*)(vbase + k0 * 64);
        #pragma unroll
        for (int i = tid; i < 512; i += 256)
            ((float4*)Vs)[i] = vsrc[i];
        __syncthreads();

        #pragma unroll 8
        for (int kk = 0; kk < 32; kk++) {
            float b4[4];
            *(float4*)&b4[0] = *(const float4*)&Vs[kk * 64 + tx * 4];
            float a[8];
            #pragma unroll
            for (int i = 0; i < 4; i++) {
                a[i]     = Ps[(ty * 4 + i) * 36 + kk];
                a[i + 4] = Ps[(64 + ty * 4 + i) * 36 + kk];
            }
            #pragma unroll
            for (int i = 0; i < 8; i++)
                #pragma unroll
                for (int j = 0; j < 4; j++)
                    acc[i][j] = fmaf(a[i], b4[j], acc[i][j]);
        }
        __syncthreads();
    }

    const int b_ = bh >> 4, h = bh & 15;
    #pragma unroll
    for (int i = 0; i < 8; i++) {
        int r = bq + ((i < 4) ? ty * 4 + i : 64 + ty * 4 + i - 4);
        float4 o = make_float4(acc[i][0], acc[i][1], acc[i][2], acc[i][3]);
        *(float4*)(g_attn + ((size_t)b_ * NT + r) * NC + h * 64 + tx * 4) = o;
    }
}

// =====================================================================
// Kernel 5: output projection.  g_proj = g_attn @ Wo + bo.
// Same 128x128x8 sgemm skeleton, plain row-major epilogue.
// =====================================================================
__global__ __launch_bounds__(256) void proj_kernel(
    const float* __restrict__ Wo, const float* __restrict__ bo)
{
    __shared__ float As[8][128];
    __shared__ float Bs[8][128];

    const int tid = threadIdx.x;
    const int bm = blockIdx.y * 128;
    const int bn = blockIdx.x * 128;

    const int arow = tid >> 1;
    const int acol = (tid & 1) * 4;
    const int brow = tid >> 5;
    const int bcol = (tid & 31) * 4;

    const float* Ap = g_attn + (size_t)(bm + arow) * NC + acol;
    const float* Bp = Wo + (size_t)brow * NC + bn + bcol;

    float acc[8][8];
    #pragma unroll
    for (int i = 0; i < 8; i++)
        #pragma unroll
        for (int j = 0; j < 8; j++) acc[i][j] = 0.f;

    const int tx = tid & 15, ty = tid >> 4;

    for (int k0 = 0; k0 < NC; k0 += 8) {
        float4 av  = *(const float4*)(Ap + k0);
        float4 bv4 = *(const float4*)(Bp + (size_t)k0 * NC);
        As[acol + 0][arow] = av.x;
        As[acol + 1][arow] = av.y;
        As[acol + 2][arow] = av.z;
        As[acol + 3][arow] = av.w;
        *(float4*)&Bs[brow][bcol] = bv4;
        __syncthreads();
        #pragma unroll
        for (int k = 0; k < 8; k++) {
            float a[8], b[8];
            *(float4*)&a[0] = *(const float4*)&As[k][ty * 4];
            *(float4*)&a[4] = *(const float4*)&As[k][64 + ty * 4];
            *(float4*)&b[0] = *(const float4*)&Bs[k][tx * 4];
            *(float4*)&b[4] = *(const float4*)&Bs[k][64 + tx * 4];
            #pragma unroll
            for (int i = 0; i < 8; i++)
                #pragma unroll
                for (int j = 0; j < 8; j++)
                    acc[i][j] = fmaf(a[i], b[j], acc[i][j]);
        }
        __syncthreads();
    }

    #pragma unroll
    for (int i = 0; i < 8; i++) {
        int m = bm + ((i < 4) ? ty * 4 + i : 64 + ty * 4 + i - 4);
        #pragma unroll
        for (int j = 0; j < 8; j++) {
            int n = bn + ((j < 4) ? tx * 4 + j : 64 + tx * 4 + j - 4);
            g_proj[(size_t)m * NC + n] = acc[i][j] + bo[n];
        }
    }
}

// =====================================================================
// Kernel 6: LayerNorm over last dim (C=1024), one block per row.
// =====================================================================
__global__ __launch_bounds__(256) void ln_kernel(
    const float* __restrict__ gamma, const float* __restrict__ beta,
    float* __restrict__ out)
{
    __shared__ float redS[8];
    __shared__ float redQ[8];
    const int tid = threadIdx.x;
    const float* p = g_proj + (size_t)blockIdx.x * NC;

    float4 v = ((const float4*)p)[tid];
    float s  = v.x + v.y + v.z + v.w;
    float ss = v.x * v.x + v.y * v.y + v.z * v.z + v.w * v.w;
    #pragma unroll
    for (int o = 16; o > 0; o >>= 1) {
        s  += __shfl_xor_sync(0xffffffffu, s,  o);
        ss += __shfl_xor_sync(0xffffffffu, ss, o);
    }
    if ((tid & 31) == 0) { redS[tid >> 5] = s; redQ[tid >> 5] = ss; }
    __syncthreads();
    float S = 0.f, Q = 0.f;
    #pragma unroll
    for (int w = 0; w < 8; w++) { S += redS[w]; Q += redQ[w]; }

    float mu  = S * (1.0f / 1024.0f);
    float var = Q * (1.0f / 1024.0f) - mu * mu;
    var = fmaxf(var, 0.0f);
    float rstd = rsqrtf(var + 1e-5f);

    float4 gv = ((const float4*)gamma)[tid];
    float4 bv = ((const float4*)beta)[tid];
    float4 o;
    o.x = (v.x - mu) * rstd * gv.x + bv.x;
    o.y = (v.y - mu) * rstd * gv.y + bv.y;
    o.z = (v.z - mu) * rstd * gv.z + bv.z;
    o.w = (v.w - mu) * rstd * gv.w + bv.w;
    ((float4*)(out + (size_t)blockIdx.x * NC))[tid] = o;
}

// =====================================================================
extern "C" void kernel_launch(void* const* d_in, const int* in_sizes, int n_in,
                              void* d_out, int out_size)
{
    const float* x    = (const float*)d_in[0];
    const int*   mask = (const int*)  d_in[1];
    const float* Wq   = (const float*)d_in[2];
    const float* bq   = (const float*)d_in[3];
    const float* Wk   = (const float*)d_in[4];
    const float* bk   = (const float*)d_in[5];
    const float* Wv   = (const float*)d_in[6];
    const float* bv   = (const float*)d_in[7];
    const float* Wo   = (const float*)d_in[8];
    const float* bo   = (const float*)d_in[9];
    const float* lg   = (const float*)d_in[10];
    const float* lb   = (const float*)d_in[11];
    float* out = (float*)d_out;

    cudaFuncSetAttribute(scores_kernel,
                         cudaFuncAttributeMaxDynamicSharedMemorySize, 69632);

    qkv_kernel   <<<dim3(8, 32, 3), 256>>>(x, Wq, bq, Wk, bk, Wv, bv);
    scores_kernel<<<dim3(8, 8, 64), 256, 68608>>>();
    softmax_kernel<<<dim3(1024, 64), 256>>>(mask);
    attnout_kernel<<<dim3(8, 64), 256>>>();
    proj_kernel  <<<dim3(8, 32), 256>>>(Wo, bo);
    ln_kernel    <<<4096, 256>>>(lg, lb, out);
}

// round 2
// speedup vs baseline: 2.2394x; 2.2394x over previous
#include <cuda_runtime.h>
#include <cstdint>

// B=4, T=1024, C=1024, H=16, D=64, BH=64
#define NT 1024
#define NC 1024

// ---------------- scratch ----------------
__device__ float g_q   [64 * 1024 * 64];        // [BH][T][D]
__device__ float g_k   [64 * 1024 * 64];        // [BH][T][D]
__device__ float g_v   [64 * 1024 * 64];        // [BH][T][D]
__device__ float g_s   [64 * 1024 * 1024];      // [BH][T][T]
__device__ float g_attn[4 * 1024 * 1024];       // [B,T,C]
__device__ float g_proj[4 * 1024 * 1024];       // [B,T,C]

// ---------------- helpers ----------------
__device__ __forceinline__ unsigned tf32r(float f) {
    unsigned u;
    asm("cvt.rna.tf32.f32 %0, %1;" : "=r"(u) : "f"(f));
    return u;
}
__device__ __forceinline__ uint4 cvt4(float4 v) {
    uint4 t;
    t.x = tf32r(v.x); t.y = tf32r(v.y); t.z = tf32r(v.z); t.w = tf32r(v.w);
    return t;
}
// D += A(16x8) * B(8x8), tf32 inputs, f32 accum
__device__ __forceinline__ void mma8(float* c, const unsigned* a, const unsigned* b) {
    asm volatile(
        "mma.sync.aligned.m16n8k8.row.col.f32.tf32.tf32.f32 "
        "{%0,%1,%2,%3}, {%4,%5,%6,%7}, {%8,%9}, {%0,%1,%2,%3};"
        : "+f"(c[0]), "+f"(c[1]), "+f"(c[2]), "+f"(c[3])
        : "r"(a[0]), "r"(a[1]), "r"(a[2]), "r"(a[3]), "r"(b[0]), "r"(b[1]));
}

// =====================================================================
// Kernel 1: fused QKV projection (tf32 mma). 128x128 tile, BK=32.
// As[m][k] stride 36, Bs[k][n] stride 132 — conflict-free frag loads.
// =====================================================================
__global__ __launch_bounds__(256) void qkv_kernel(
    const float* __restrict__ x,
    const float* __restrict__ Wq, const float* __restrict__ bq,
    const float* __restrict__ Wk, const float* __restrict__ bk,
    const float* __restrict__ Wv, const float* __restrict__ bv)
{
    __shared__ unsigned As[128 * 36];
    __shared__ unsigned Bs[32 * 132];

    const int z = blockIdx.z;
    const float* __restrict__ W    = (z == 0) ? Wq : (z == 1) ? Wk : Wv;
    const float* __restrict__ bias = (z == 0) ? bq : (z == 1) ? bk : bv;

    const int tid  = threadIdx.x;
    const int wid  = tid >> 5, lane = tid & 31;
    const int g    = lane >> 2, tg = lane & 3;
    const int bm   = blockIdx.y * 128, bn = blockIdx.x * 128;
    const int wm   = wid & 1, wn = wid >> 1;

    const int ar = tid >> 3, ac = (tid & 7) * 4;     // A producer: row ar+32i, col ac
    const int br = tid >> 5, bc = (tid & 31) * 4;    // B producer: row br+8i, col bc

    float4 aR[4], bR[4];
    #pragma unroll
    for (int i = 0; i < 4; i++) {
        aR[i] = *(const float4*)(x + (size_t)(bm + ar + 32 * i) * NC + ac);
        bR[i] = *(const float4*)(W + (size_t)(br + 8 * i) * NC + bn + bc);
    }

    float acc[4][4][4];
    #pragma unroll
    for (int a = 0; a < 4; a++)
        #pragma unroll
        for (int b = 0; b < 4; b++)
            #pragma unroll
            for (int c = 0; c < 4; c++) acc[a][b][c] = 0.f;

    for (int kt = 0; kt < 32; ++kt) {
        #pragma unroll
        for (int i = 0; i < 4; i++) {
            *(uint4*)&As[(ar + 32 * i) * 36 + ac] = cvt4(aR[i]);
            *(uint4*)&Bs[(br + 8 * i) * 132 + bc] = cvt4(bR[i]);
        }
        __syncthreads();
        if (kt < 31) {
            int k0 = (kt + 1) * 32;
            #pragma unroll
            for (int i = 0; i < 4; i++) {
                aR[i] = *(const float4*)(x + (size_t)(bm + ar + 32 * i) * NC + k0 + ac);
                bR[i] = *(const float4*)(W + (size_t)(k0 + br + 8 * i) * NC + bn + bc);
            }
        }
        #pragma unroll
        for (int ks = 0; ks < 4; ks++) {
            const int k = ks * 8;
            unsigned af[4][4], bf[4][2];
            #pragma unroll
            for (int mt = 0; mt < 4; mt++) {
                int r0 = (wm * 64 + mt * 16 + g) * 36;
                af[mt][0] = As[r0 + k + tg];
                af[mt][1] = As[r0 + 8 * 36 + k + tg];
                af[mt][2] = As[r0 + k + tg + 4];
                af[mt][3] = As[r0 + 8 * 36 + k + tg + 4];
            }
            #pragma unroll
            for (int nt = 0; nt < 4; nt++) {
                int c0 = wn * 32 + nt * 8 + g;
                bf[nt][0] = Bs[(k + tg) * 132 + c0];
                bf[nt][1] = Bs[(k + tg + 4) * 132 + c0];
            }
            #pragma unroll
            for (int mt = 0; mt < 4; mt++)
                #pragma unroll
                for (int nt = 0; nt < 4; nt++)
                    mma8(acc[mt][nt], af[mt], bf[nt]);
        }
        __syncthreads();
    }

    #pragma unroll
    for (int mt = 0; mt < 4; mt++) {
        #pragma unroll
        for (int nt = 0; nt < 4; nt++) {
            int row = bm + wm * 64 + mt * 16 + g;
            int col = bn + wn * 32 + nt * 8 + tg * 2;
            float b0 = bias[col], b1 = bias[col + 1];
            #pragma unroll
            for (int hf = 0; hf < 2; hf++) {
                int m  = row + hf * 8;
                int bb = m >> 10, t = m & 1023;
                int h  = col >> 6, d = col & 63;
                int bh = bb * 16 + h;
                float2 val = make_float2(acc[mt][nt][hf * 2 + 0] + b0,
                                         acc[mt][nt][hf * 2 + 1] + b1);
                size_t o = ((size_t)(bh * 1024 + t)) * 64 + d;
                if (z == 0)      *(float2*)&g_q[o] = val;
                else if (z == 1) *(float2*)&g_k[o] = val;
                else             *(float2*)&g_v[o] = val;
            }
        }
    }
}

// =====================================================================
// Kernel 2: scores (tf32 mma). 128q x 128k per block, full D=64.
// Qs/Ks row-major stride 68, conflict-free frag loads.
// =====================================================================
__global__ __launch_bounds__(256) void scores_kernel()
{
    extern __shared__ unsigned sm2[];
    unsigned* Qs = sm2;             // [128][68]
    unsigned* Ks = sm2 + 128 * 68;  // [128][68]

    const int bh = blockIdx.z;
    const int bq = blockIdx.y * 128;
    const int bk = blockIdx.x * 128;
    const int tid = threadIdx.x;
    const int wid = tid >> 5, lane = tid & 31;
    const int g   = lane >> 2, tg = lane & 3;
    const int wm  = wid & 1, wn = wid >> 1;

    const float* qptr = g_q + ((size_t)bh * NT + bq) * 64;
    const float* kptr = g_k + ((size_t)bh * NT + bk) * 64;

    #pragma unroll
    for (int i = 0; i < 8; i++) {
        int idx = tid + 256 * i;
        int r = idx >> 4, c = (idx & 15) * 4;
        *(uint4*)&Qs[r * 68 + c] = cvt4(*(const float4*)(qptr + r * 64 + c));
        *(uint4*)&Ks[r * 68 + c] = cvt4(*(const float4*)(kptr + r * 64 + c));
    }
    __syncthreads();

    float acc[4][4][4];
    #pragma unroll
    for (int a = 0; a < 4; a++)
        #pragma unroll
        for (int b = 0; b < 4; b++)
            #pragma unroll
            for (int c = 0; c < 4; c++) acc[a][b][c] = 0.f;

    #pragma unroll
    for (int ks = 0; ks < 8; ks++) {
        const int k = ks * 8;
        unsigned af[4][4], bf[4][2];
        #pragma unroll
        for (int mt = 0; mt < 4; mt++) {
            int r0 = (wm * 64 + mt * 16 + g) * 68;
            af[mt][0] = Qs[r0 + k + tg];
            af[mt][1] = Qs[r0 + 8 * 68 + k + tg];
            af[mt][2] = Qs[r0 + k + tg + 4];
            af[mt][3] = Qs[r0 + 8 * 68 + k + tg + 4];
        }
        #pragma unroll
        for (int nt = 0; nt < 4; nt++) {
            int c0 = (wn * 32 + nt * 8 + g) * 68;
            bf[nt][0] = Ks[c0 + k + tg];
            bf[nt][1] = Ks[c0 + k + tg + 4];
        }
        #pragma unroll
        for (int mt = 0; mt < 4; mt++)
            #pragma unroll
            for (int nt = 0; nt < 4; nt++)
                mma8(acc[mt][nt], af[mt], bf[nt]);
    }

    const float scale = 0.125f;
    #pragma unroll
    for (int mt = 0; mt < 4; mt++) {
        #pragma unroll
        for (int nt = 0; nt < 4; nt++) {
            int q0  = bq + wm * 64 + mt * 16 + g;
            int col = bk + wn * 32 + nt * 8 + tg * 2;
            #pragma unroll
            for (int hf = 0; hf < 2; hf++) {
                float2 val = make_float2(acc[mt][nt][hf * 2 + 0] * scale,
                                         acc[mt][nt][hf * 2 + 1] * scale);
                size_t o = ((size_t)(bh * 1024 + q0 + hf * 8)) * 1024 + col;
                *(float2*)&g_s[o] = val;
            }
        }
    }
}

// =====================================================================
// Kernel 3: mask + softmax (unchanged).
// =====================================================================
__global__ __launch_bounds__(256) void softmax_kernel(const int* __restrict__ mask)
{
    __shared__ float red[8];
    const int tid = threadIdx.x;
    float* p = g_s + ((size_t)blockIdx.y * NT + blockIdx.x) * NT;
    const int* m = mask + (blockIdx.y >> 4) * NT;

    float4 v = ((const float4*)p)[tid];
    int4  mk = ((const int4*)m)[tid];
    if (mk.x == 0) v.x = -1e30f;
    if (mk.y == 0) v.y = -1e30f;
    if (mk.z == 0) v.z = -1e30f;
    if (mk.w == 0) v.w = -1e30f;

    float mx = fmaxf(fmaxf(v.x, v.y), fmaxf(v.z, v.w));
    #pragma unroll
    for (int o = 16; o > 0; o >>= 1) mx = fmaxf(mx, __shfl_xor_sync(0xffffffffu, mx, o));
    if ((tid & 31) == 0) red[tid >> 5] = mx;
    __syncthreads();
    float bmx = red[0];
    #pragma unroll
    for (int w = 1; w < 8; w++) bmx = fmaxf(bmx, red[w]);
    __syncthreads();

    v.x = __expf(v.x - bmx);
    v.y = __expf(v.y - bmx);
    v.z = __expf(v.z - bmx);
    v.w = __expf(v.w - bmx);
    float s = v.x + v.y + v.z + v.w;
    #pragma unroll
    for (int o = 16; o > 0; o >>= 1) s += __shfl_xor_sync(0xffffffffu, s, o);
    if ((tid & 31) == 0) red[tid >> 5] = s;
    __syncthreads();
    float tot = 0.f;
    #pragma unroll
    for (int w = 0; w < 8; w++) tot += red[w];

    float inv = 1.0f / tot;
    v.x *= inv; v.y *= inv; v.z *= inv; v.w *= inv;
    ((float4*)p)[tid] = v;
}

// =====================================================================
// Kernel 4: O = P @ V (tf32 mma). 128q x 64d per block, BK=32.
// =====================================================================
__global__ __launch_bounds__(256) void attnout_kernel()
{
    __shared__ unsigned Ps[128 * 36];
    __shared__ unsigned Vs[32 * 68];

    const int bh = blockIdx.y;
    const int bq = blockIdx.x * 128;
    const int tid = threadIdx.x;
    const int wid = tid >> 5, lane = tid & 31;
    const int g   = lane >> 2, tg = lane & 3;
    const int wm  = wid & 3, wn = wid >> 2;

    const float* srow  = g_s + ((size_t)bh * NT + bq) * NT;
    const float* vbase = g_v + (size_t)bh * NT * 64;

    const int pr = tid >> 3, pc = (tid & 7) * 4;     // P producer: row pr+32i
    const int vr = tid >> 4, vc = (tid & 15) * 4;    // V producer: row vr+16i

    float4 pR[4], vR[2];
    #pragma unroll
    for (int i = 0; i < 4; i++)
        pR[i] = *(const float4*)(srow + (size_t)(pr + 32 * i) * NT + pc);
    #pragma unroll
    for (int i = 0; i < 2; i++)
        vR[i] = *(const float4*)(vbase + (size_t)(vr + 16 * i) * 64 + vc);

    float acc[2][4][4];
    #pragma unroll
    for (int a = 0; a < 2; a++)
        #pragma unroll
        for (int b = 0; b < 4; b++)
            #pragma unroll
            for (int c = 0; c < 4; c++) acc[a][b][c] = 0.f;

    for (int kt = 0; kt < 32; ++kt) {
        #pragma unroll
        for (int i = 0; i < 4; i++)
            *(uint4*)&Ps[(pr + 32 * i) * 36 + pc] = cvt4(pR[i]);
        #pragma unroll
        for (int i = 0; i < 2; i++)
            *(uint4*)&Vs[(vr + 16 * i) * 68 + vc] = cvt4(vR[i]);
        __syncthreads();
        if (kt < 31) {
            int k0 = (kt + 1) * 32;
            #pragma unroll
            for (int i = 0; i < 4; i++)
                pR[i] = *(const float4*)(srow + (size_t)(pr + 32 * i) * NT + k0 + pc);
            #pragma unroll
            for (int i = 0; i < 2; i++)
                vR[i] = *(const float4*)(vbase + (size_t)(k0 + vr + 16 * i) * 64 + vc);
        }
        #pragma unroll
        for (int ks = 0; ks < 4; ks++) {
            const int k = ks * 8;
            unsigned af[2][4], bf[4][2];
            #pragma unroll
            for (int mt = 0; mt < 2; mt++) {
                int r0 = (wm * 32 + mt * 16 + g) * 36;
                af[mt][0] = Ps[r0 + k + tg];
                af[mt][1] = Ps[r0 + 8 * 36 + k + tg];
                af[mt][2] = Ps[r0 + k + tg + 4];
                af[mt][3] = Ps[r0 + 8 * 36 + k + tg + 4];
            }
            #pragma unroll
            for (int nt = 0; nt < 4; nt++) {
                int c0 = wn * 32 + nt * 8 + g;
                bf[nt][0] = Vs[(k + tg) * 68 + c0];
                bf[nt][1] = Vs[(k + tg + 4) * 68 + c0];
            }
            #pragma unroll
            for (int mt = 0; mt < 2; mt++)
                #pragma unroll
                for (int nt = 0; nt < 4; nt++)
                    mma8(acc[mt][nt], af[mt], bf[nt]);
        }
        __syncthreads();
    }

    const int b_ = bh >> 4, h = bh & 15;
    #pragma unroll
    for (int mt = 0; mt < 2; mt++) {
        #pragma unroll
        for (int nt = 0; nt < 4; nt++) {
            int d = wn * 32 + nt * 8 + tg * 2;
            #pragma unroll
            for (int hf = 0; hf < 2; hf++) {
                int q = bq + wm * 32 + mt * 16 + g + hf * 8;
                float2 val = make_float2(acc[mt][nt][hf * 2 + 0],
                                         acc[mt][nt][hf * 2 + 1]);
                *(float2*)&g_attn[((size_t)(b_ * 1024 + q)) * NC + h * 64 + d] = val;
            }
        }
    }
}

// =====================================================================
// Kernel 5: output projection (tf32 mma), same skeleton as qkv.
// =====================================================================
__global__ __launch_bounds__(256) void proj_kernel(
    const float* __restrict__ Wo, const float* __restrict__ bo)
{
    __shared__ unsigned As[128 * 36];
    __shared__ unsigned Bs[32 * 132];

    const int tid  = threadIdx.x;
    const int wid  = tid >> 5, lane = tid & 31;
    const int g    = lane >> 2, tg = lane & 3;
    const int bm   = blockIdx.y * 128, bn = blockIdx.x * 128;
    const int wm   = wid & 1, wn = wid >> 1;

    const int ar = tid >> 3, ac = (tid & 7) * 4;
    const int br = tid >> 5, bc = (tid & 31) * 4;

    float4 aR[4], bR[4];
    #pragma unroll
    for (int i = 0; i < 4; i++) {
        aR[i] = *(const float4*)(g_attn + (size_t)(bm + ar + 32 * i) * NC + ac);
        bR[i] = *(const float4*)(Wo + (size_t)(br + 8 * i) * NC + bn + bc);
    }

    float acc[4][4][4];
    #pragma unroll
    for (int a = 0; a < 4; a++)
        #pragma unroll
        for (int b = 0; b < 4; b++)
            #pragma unroll
            for (int c = 0; c < 4; c++) acc[a][b][c] = 0.f;

    for (int kt = 0; kt < 32; ++kt) {
        #pragma unroll
        for (int i = 0; i < 4; i++) {
            *(uint4*)&As[(ar + 32 * i) * 36 + ac] = cvt4(aR[i]);
            *(uint4*)&Bs[(br + 8 * i) * 132 + bc] = cvt4(bR[i]);
        }
        __syncthreads();
        if (kt < 31) {
            int k0 = (kt + 1) * 32;
            #pragma unroll
            for (int i = 0; i < 4; i++) {
                aR[i] = *(const float4*)(g_attn + (size_t)(bm + ar + 32 * i) * NC + k0 + ac);
                bR[i] = *(const float4*)(Wo + (size_t)(k0 + br + 8 * i) * NC + bn + bc);
            }
        }
        #pragma unroll
        for (int ks = 0; ks < 4; ks++) {
            const int k = ks * 8;
            unsigned af[4][4], bf[4][2];
            #pragma unroll
            for (int mt = 0; mt < 4; mt++) {
                int r0 = (wm * 64 + mt * 16 + g) * 36;
                af[mt][0] = As[r0 + k + tg];
                af[mt][1] = As[r0 + 8 * 36 + k + tg];
                af[mt][2] = As[r0 + k + tg + 4];
                af[mt][3] = As[r0 + 8 * 36 + k + tg + 4];
            }
            #pragma unroll
            for (int nt = 0; nt < 4; nt++) {
                int c0 = wn * 32 + nt * 8 + g;
                bf[nt][0] = Bs[(k + tg) * 132 + c0];
                bf[nt][1] = Bs[(k + tg + 4) * 132 + c0];
            }
            #pragma unroll
            for (int mt = 0; mt < 4; mt++)
                #pragma unroll
                for (int nt = 0; nt < 4; nt++)
                    mma8(acc[mt][nt], af[mt], bf[nt]);
        }
        __syncthreads();
    }

    #pragma unroll
    for (int mt = 0; mt < 4; mt++) {
        #pragma unroll
        for (int nt = 0; nt < 4; nt++) {
            int row = bm + wm * 64 + mt * 16 + g;
            int col = bn + wn * 32 + nt * 8 + tg * 2;
            float b0 = bo[col], b1 = bo[col + 1];
            #pragma unroll
            for (int hf = 0; hf < 2; hf++) {
                int m = row + hf * 8;
                float2 val = make_float2(acc[mt][nt][hf * 2 + 0] + b0,
                                         acc[mt][nt][hf * 2 + 1] + b1);
                *(float2*)&g_proj[(size_t)m * NC + col] = val;
            }
        }
    }
}

// =====================================================================
// Kernel 6: LayerNorm (unchanged).
// =====================================================================
__global__ __launch_bounds__(256) void ln_kernel(
    const float* __restrict__ gamma, const float* __restrict__ beta,
    float* __restrict__ out)
{
    __shared__ float redS[8];
    __shared__ float redQ[8];
    const int tid = threadIdx.x;
    const float* p = g_proj + (size_t)blockIdx.x * NC;

    float4 v = ((const float4*)p)[tid];
    float s  = v.x + v.y + v.z + v.w;
    float ss = v.x * v.x + v.y * v.y + v.z * v.z + v.w * v.w;
    #pragma unroll
    for (int o = 16; o > 0; o >>= 1) {
        s  += __shfl_xor_sync(0xffffffffu, s,  o);
        ss += __shfl_xor_sync(0xffffffffu, ss, o);
    }
    if ((tid & 31) == 0) { redS[tid >> 5] = s; redQ[tid >> 5] = ss; }
    __syncthreads();
    float S = 0.f, Q = 0.f;
    #pragma unroll
    for (int w = 0; w < 8; w++) { S += redS[w]; Q += redQ[w]; }

    float mu  = S * (1.0f / 1024.0f);
    float var = Q * (1.0f / 1024.0f) - mu * mu;
    var = fmaxf(var, 0.0f);
    float rstd = rsqrtf(var + 1e-5f);

    float4 gv = ((const float4*)gamma)[tid];
    float4 bv = ((const float4*)beta)[tid];
    float4 o;
    o.x = (v.x - mu) * rstd * gv.x + bv.x;
    o.y = (v.y - mu) * rstd * gv.y + bv.y;
    o.z = (v.z - mu) * rstd * gv.z + bv.z;
    o.w = (v.w - mu) * rstd * gv.w + bv.w;
    ((float4*)(out + (size_t)blockIdx.x * NC))[tid] = o;
}

// =====================================================================
extern "C" void kernel_launch(void* const* d_in, const int* in_sizes, int n_in,
                              void* d_out, int out_size)
{
    const float* x    = (const float*)d_in[0];
    const int*   mask = (const int*)  d_in[1];
    const float* Wq   = (const float*)d_in[2];
    const float* bq   = (const float*)d_in[3];
    const float* Wk   = (const float*)d_in[4];
    const float* bk   = (const float*)d_in[5];
    const float* Wv   = (const float*)d_in[6];
    const float* bv   = (const float*)d_in[7];
    const float* Wo   = (const float*)d_in[8];
    const float* bo   = (const float*)d_in[9];
    const float* lg   = (const float*)d_in[10];
    const float* lb   = (const float*)d_in[11];
    float* out = (float*)d_out;

    cudaFuncSetAttribute(scores_kernel,
                         cudaFuncAttributeMaxDynamicSharedMemorySize, 69632);

    qkv_kernel    <<<dim3(8, 32, 3), 256>>>(x, Wq, bq, Wk, bk, Wv, bv);
    scores_kernel <<<dim3(8, 8, 64), 256, 69632>>>();
    softmax_kernel<<<dim3(1024, 64), 256>>>(mask);
    attnout_kernel<<<dim3(8, 64), 256>>>();
    proj_kernel   <<<dim3(8, 32), 256>>>(Wo, bo);
    ln_kernel     <<<4096, 256>>>(lg, lb, out);
}

// round 3
// speedup vs baseline: 2.6274x; 1.1733x over previous
#include <cuda_runtime.h>
#include <cstdint>

// B=4, T=1024, C=1024, H=16, D=64, BH=64
#define NT 1024
#define NC 1024

// ---------------- scratch ----------------
__device__ float g_q   [64 * 1024 * 64];        // [BH][T][D]  (pre-scaled by 1/8)
__device__ float g_k   [64 * 1024 * 64];        // [BH][T][D]
__device__ float g_v   [64 * 1024 * 64];        // [BH][T][D]
__device__ float g_attn[4 * 1024 * 1024];       // [B,T,C]
__device__ float g_proj[4 * 1024 * 1024];       // [B,T,C]

// ---------------- helpers ----------------
__device__ __forceinline__ unsigned tf32r(float f) {
    unsigned u;
    asm("cvt.rna.tf32.f32 %0, %1;" : "=r"(u) : "f"(f));
    return u;
}
__device__ __forceinline__ uint4 cvt4(float4 v) {
    uint4 t;
    t.x = tf32r(v.x); t.y = tf32r(v.y); t.z = tf32r(v.z); t.w = tf32r(v.w);
    return t;
}
__device__ __forceinline__ void mma8(float* c, const unsigned* a, const unsigned* b) {
    asm volatile(
        "mma.sync.aligned.m16n8k8.row.col.f32.tf32.tf32.f32 "
        "{%0,%1,%2,%3}, {%4,%5,%6,%7}, {%8,%9}, {%0,%1,%2,%3};"
        : "+f"(c[0]), "+f"(c[1]), "+f"(c[2]), "+f"(c[3])
        : "r"(a[0]), "r"(a[1]), "r"(a[2]), "r"(a[3]), "r"(b[0]), "r"(b[1]));
}

// =====================================================================
// Kernel 1: fused QKV projection (tf32 mma). 128x128 tile, BK=32.
// Q output is pre-scaled by 1/sqrt(D)=0.125 (folded into flash QK^T).
// =====================================================================
__global__ __launch_bounds__(256) void qkv_kernel(
    const float* __restrict__ x,
    const float* __restrict__ Wq, const float* __restrict__ bq,
    const float* __restrict__ Wk, const float* __restrict__ bk,
    const float* __restrict__ Wv, const float* __restrict__ bv)
{
    __shared__ unsigned As[128 * 36];
    __shared__ unsigned Bs[32 * 132];

    const int z = blockIdx.z;
    const float* __restrict__ W    = (z == 0) ? Wq : (z == 1) ? Wk : Wv;
    const float* __restrict__ bias = (z == 0) ? bq : (z == 1) ? bk : bv;

    const int tid  = threadIdx.x;
    const int wid  = tid >> 5, lane = tid & 31;
    const int g    = lane >> 2, tg = lane & 3;
    const int bm   = blockIdx.y * 128, bn = blockIdx.x * 128;
    const int wm   = wid & 1, wn = wid >> 1;

    const int ar = tid >> 3, ac = (tid & 7) * 4;
    const int br = tid >> 5, bc = (tid & 31) * 4;

    float4 aR[4], bR[4];
    #pragma unroll
    for (int i = 0; i < 4; i++) {
        aR[i] = *(const float4*)(x + (size_t)(bm + ar + 32 * i) * NC + ac);
        bR[i] = *(const float4*)(W + (size_t)(br + 8 * i) * NC + bn + bc);
    }

    float acc[4][4][4];
    #pragma unroll
    for (int a = 0; a < 4; a++)
        #pragma unroll
        for (int b = 0; b < 4; b++)
            #pragma unroll
            for (int c = 0; c < 4; c++) acc[a][b][c] = 0.f;

    for (int kt = 0; kt < 32; ++kt) {
        #pragma unroll
        for (int i = 0; i < 4; i++) {
            *(uint4*)&As[(ar + 32 * i) * 36 + ac] = cvt4(aR[i]);
            *(uint4*)&Bs[(br + 8 * i) * 132 + bc] = cvt4(bR[i]);
        }
        __syncthreads();
        if (kt < 31) {
            int k0 = (kt + 1) * 32;
            #pragma unroll
            for (int i = 0; i < 4; i++) {
                aR[i] = *(const float4*)(x + (size_t)(bm + ar + 32 * i) * NC + k0 + ac);
                bR[i] = *(const float4*)(W + (size_t)(k0 + br + 8 * i) * NC + bn + bc);
            }
        }
        #pragma unroll
        for (int ks = 0; ks < 4; ks++) {
            const int k = ks * 8;
            unsigned af[4][4], bf[4][2];
            #pragma unroll
            for (int mt = 0; mt < 4; mt++) {
                int r0 = (wm * 64 + mt * 16 + g) * 36;
                af[mt][0] = As[r0 + k + tg];
                af[mt][1] = As[r0 + 8 * 36 + k + tg];
                af[mt][2] = As[r0 + k + tg + 4];
                af[mt][3] = As[r0 + 8 * 36 + k + tg + 4];
            }
            #pragma unroll
            for (int nt = 0; nt < 4; nt++) {
                int c0 = wn * 32 + nt * 8 + g;
                bf[nt][0] = Bs[(k + tg) * 132 + c0];
                bf[nt][1] = Bs[(k + tg + 4) * 132 + c0];
            }
            #pragma unroll
            for (int mt = 0; mt < 4; mt++)
                #pragma unroll
                for (int nt = 0; nt < 4; nt++)
                    mma8(acc[mt][nt], af[mt], bf[nt]);
        }
        __syncthreads();
    }

    #pragma unroll
    for (int mt = 0; mt < 4; mt++) {
        #pragma unroll
        for (int nt = 0; nt < 4; nt++) {
            int row = bm + wm * 64 + mt * 16 + g;
            int col = bn + wn * 32 + nt * 8 + tg * 2;
            float b0 = bias[col], b1 = bias[col + 1];
            #pragma unroll
            for (int hf = 0; hf < 2; hf++) {
                int m  = row + hf * 8;
                int bb = m >> 10, t = m & 1023;
                int h  = col >> 6, d = col & 63;
                int bh = bb * 16 + h;
                float2 val = make_float2(acc[mt][nt][hf * 2 + 0] + b0,
                                         acc[mt][nt][hf * 2 + 1] + b1);
                size_t o = ((size_t)(bh * 1024 + t)) * 64 + d;
                if (z == 0) {
                    val.x *= 0.125f; val.y *= 0.125f;   // fold 1/sqrt(D)
                    *(float2*)&g_q[o] = val;
                }
                else if (z == 1) *(float2*)&g_k[o] = val;
                else             *(float2*)&g_v[o] = val;
            }
        }
    }
}

// =====================================================================
// Kernel 2: FLASH attention — scores + mask + online softmax + P@V
// fused.  One block = 128 q-rows of one head; loop over 8 k-tiles.
// Warp w owns q-rows [w*16, w*16+16).
// =====================================================================
__global__ __launch_bounds__(256, 1) void flash_kernel(const int* __restrict__ mask)
{
    extern __shared__ unsigned sm[];
    unsigned* Qs = sm;                    // [128][68] tf32, pre-scaled
    unsigned* Ks = Qs + 128 * 68;         // [128][68]
    unsigned* Vs = Ks + 128 * 68;         // [128][68]
    unsigned* Ps = Vs + 128 * 68;         // [128][132]
    int*      Ms = (int*)(Ps + 128 * 132);// [128]

    const int bh  = blockIdx.y;
    const int bq  = blockIdx.x * 128;
    const int tid = threadIdx.x;
    const int w   = tid >> 5, lane = tid & 31;
    const int g   = lane >> 2, tg = lane & 3;

    const float* qptr  = g_q + ((size_t)bh * NT + bq) * 64;
    const float* kbase = g_k + (size_t)bh * NT * 64;
    const float* vbase = g_v + (size_t)bh * NT * 64;
    const int*   mrow  = mask + (bh >> 4) * NT;

    // load Q tile once
    #pragma unroll
    for (int i = 0; i < 8; i++) {
        int idx = tid + 256 * i;
        int r = idx >> 4, c = (idx & 15) * 4;
        *(uint4*)&Qs[r * 68 + c] = cvt4(*(const float4*)(qptr + r * 64 + c));
    }

    float m0 = -1e30f, m1 = -1e30f, l0 = 0.f, l1 = 0.f;
    float o[8][4];
    #pragma unroll
    for (int i = 0; i < 8; i++)
        #pragma unroll
        for (int j = 0; j < 4; j++) o[i][j] = 0.f;

    const int r0q = (w * 16 + g) * 68;      // Qs row offsets for this thread
    const int r1q = (w * 16 + 8 + g) * 68;
    const int r0p = (w * 16 + g) * 132;
    const int r1p = (w * 16 + 8 + g) * 132;

    for (int t0 = 0; t0 < NT; t0 += 128) {
        // ---- load K/V tile + mask ----
        #pragma unroll
        for (int i = 0; i < 8; i++) {
            int idx = tid + 256 * i;
            int r = idx >> 4, c = (idx & 15) * 4;
            *(uint4*)&Ks[r * 68 + c] = cvt4(*(const float4*)(kbase + (size_t)(t0 + r) * 64 + c));
            *(uint4*)&Vs[r * 68 + c] = cvt4(*(const float4*)(vbase + (size_t)(t0 + r) * 64 + c));
        }
        if (tid < 128) Ms[tid] = mrow[t0 + tid];
        __syncthreads();

        // ---- S = Q @ K^T  (warp: 16 x 128) ----
        float s[16][4];
        #pragma unroll
        for (int nt = 0; nt < 16; nt++)
            #pragma unroll
            for (int c = 0; c < 4; c++) s[nt][c] = 0.f;

        #pragma unroll
        for (int ks = 0; ks < 8; ks++) {
            const int k = ks * 8;
            unsigned af[4];
            af[0] = Qs[r0q + k + tg];
            af[1] = Qs[r1q + k + tg];
            af[2] = Qs[r0q + k + tg + 4];
            af[3] = Qs[r1q + k + tg + 4];
            #pragma unroll
            for (int nt = 0; nt < 16; nt++) {
                unsigned bf[2];
                bf[0] = Ks[(nt * 8 + g) * 68 + k + tg];
                bf[1] = Ks[(nt * 8 + g) * 68 + k + tg + 4];
                mma8(s[nt], af, bf);
            }
        }

        // ---- mask + row max ----
        float tmax0 = -1e30f, tmax1 = -1e30f;
        #pragma unroll
        for (int nt = 0; nt < 16; nt++) {
            int c0 = nt * 8 + tg * 2;
            int mk0 = Ms[c0], mk1 = Ms[c0 + 1];
            if (mk0 == 0) { s[nt][0] = -1e30f; s[nt][2] = -1e30f; }
            if (mk1 == 0) { s[nt][1] = -1e30f; s[nt][3] = -1e30f; }
            tmax0 = fmaxf(tmax0, fmaxf(s[nt][0], s[nt][1]));
            tmax1 = fmaxf(tmax1, fmaxf(s[nt][2], s[nt][3]));
        }
        #pragma unroll
        for (int off = 1; off <= 2; off <<= 1) {
            tmax0 = fmaxf(tmax0, __shfl_xor_sync(0xffffffffu, tmax0, off));
            tmax1 = fmaxf(tmax1, __shfl_xor_sync(0xffffffffu, tmax1, off));
        }

        float nm0 = fmaxf(m0, tmax0);
        float nm1 = fmaxf(m1, tmax1);
        float cor0 = __expf(m0 - nm0);
        float cor1 = __expf(m1 - nm1);
        m0 = nm0; m1 = nm1;

        // ---- P = exp(S - m), store tf32 to smem; accumulate row sums ----
        float sum0 = 0.f, sum1 = 0.f;
        #pragma unroll
        for (int nt = 0; nt < 16; nt++) {
            float p0 = __expf(s[nt][0] - m0);
            float p1 = __expf(s[nt][1] - m0);
            float p2 = __expf(s[nt][2] - m1);
            float p3 = __expf(s[nt][3] - m1);
            sum0 += p0 + p1;
            sum1 += p2 + p3;
            int c0 = nt * 8 + tg * 2;
            uint2 u01 = make_uint2(tf32r(p0), tf32r(p1));
            uint2 u23 = make_uint2(tf32r(p2), tf32r(p3));
            *(uint2*)&Ps[r0p + c0] = u01;
            *(uint2*)&Ps[r1p + c0] = u23;
        }
        #pragma unroll
        for (int off = 1; off <= 2; off <<= 1) {
            sum0 += __shfl_xor_sync(0xffffffffu, sum0, off);
            sum1 += __shfl_xor_sync(0xffffffffu, sum1, off);
        }
        l0 = l0 * cor0 + sum0;
        l1 = l1 * cor1 + sum1;

        // rescale O accumulators
        #pragma unroll
        for (int nt = 0; nt < 8; nt++) {
            o[nt][0] *= cor0; o[nt][1] *= cor0;
            o[nt][2] *= cor1; o[nt][3] *= cor1;
        }
        __syncthreads();   // Ps visible to whole warp set; Ks free

        // ---- O += P @ V  (warp: 16 x 64, k=128) ----
        #pragma unroll
        for (int ks = 0; ks < 16; ks++) {
            const int k = ks * 8;
            unsigned af[4];
            af[0] = Ps[r0p + k + tg];
            af[1] = Ps[r1p + k + tg];
            af[2] = Ps[r0p + k + tg + 4];
            af[3] = Ps[r1p + k + tg + 4];
            #pragma unroll
            for (int nt = 0; nt < 8; nt++) {
                unsigned bf[2];
                bf[0] = Vs[(k + tg) * 68 + nt * 8 + g];
                bf[1] = Vs[(k + tg + 4) * 68 + nt * 8 + g];
                mma8(o[nt], af, bf);
            }
        }
        __syncthreads();   // done with Ks/Vs/Ps before next tile overwrites
    }

    // ---- epilogue: O / l, write merged-head layout ----
    const int b_ = bh >> 4, h = bh & 15;
    float inv0 = 1.0f / l0, inv1 = 1.0f / l1;
    #pragma unroll
    for (int nt = 0; nt < 8; nt++) {
        int d = nt * 8 + tg * 2;
        int q0 = bq + w * 16 + g;
        float2 v0 = make_float2(o[nt][0] * inv0, o[nt][1] * inv0);
        float2 v1 = make_float2(o[nt][2] * inv1, o[nt][3] * inv1);
        *(float2*)&g_attn[((size_t)(b_ * 1024 + q0)) * NC + h * 64 + d]     = v0;
        *(float2*)&g_attn[((size_t)(b_ * 1024 + q0 + 8)) * NC + h * 64 + d] = v1;
    }
}

// =====================================================================
// Kernel 3: output projection (tf32 mma).
// =====================================================================
__global__ __launch_bounds__(256) void proj_kernel(
    const float* __restrict__ Wo, const float* __restrict__ bo)
{
    __shared__ unsigned As[128 * 36];
    __shared__ unsigned Bs[32 * 132];

    const int tid  = threadIdx.x;
    const int wid  = tid >> 5, lane = tid & 31;
    const int g    = lane >> 2, tg = lane & 3;
    const int bm   = blockIdx.y * 128, bn = blockIdx.x * 128;
    const int wm   = wid & 1, wn = wid >> 1;

    const int ar = tid >> 3, ac = (tid & 7) * 4;
    const int br = tid >> 5, bc = (tid & 31) * 4;

    float4 aR[4], bR[4];
    #pragma unroll
    for (int i = 0; i < 4; i++) {
        aR[i] = *(const float4*)(g_attn + (size_t)(bm + ar + 32 * i) * NC + ac);
        bR[i] = *(const float4*)(Wo + (size_t)(br + 8 * i) * NC + bn + bc);
    }

    float acc[4][4][4];
    #pragma unroll
    for (int a = 0; a < 4; a++)
        #pragma unroll
        for (int b = 0; b < 4; b++)
            #pragma unroll
            for (int c = 0; c < 4; c++) acc[a][b][c] = 0.f;

    for (int kt = 0; kt < 32; ++kt) {
        #pragma unroll
        for (int i = 0; i < 4; i++) {
            *(uint4*)&As[(ar + 32 * i) * 36 + ac] = cvt4(aR[i]);
            *(uint4*)&Bs[(br + 8 * i) * 132 + bc] = cvt4(bR[i]);
        }
        __syncthreads();
        if (kt < 31) {
            int k0 = (kt + 1) * 32;
            #pragma unroll
            for (int i = 0; i < 4; i++) {
                aR[i] = *(const float4*)(g_attn + (size_t)(bm + ar + 32 * i) * NC + k0 + ac);
                bR[i] = *(const float4*)(Wo + (size_t)(k0 + br + 8 * i) * NC + bn + bc);
            }
        }
        #pragma unroll
        for (int ks = 0; ks < 4; ks++) {
            const int k = ks * 8;
            unsigned af[4][4], bf[4][2];
            #pragma unroll
            for (int mt = 0; mt < 4; mt++) {
                int r0 = (wm * 64 + mt * 16 + g) * 36;
                af[mt][0] = As[r0 + k + tg];
                af[mt][1] = As[r0 + 8 * 36 + k + tg];
                af[mt][2] = As[r0 + k + tg + 4];
                af[mt][3] = As[r0 + 8 * 36 + k + tg + 4];
            }
            #pragma unroll
            for (int nt = 0; nt < 4; nt++) {
                int c0 = wn * 32 + nt * 8 + g;
                bf[nt][0] = Bs[(k + tg) * 132 + c0];
                bf[nt][1] = Bs[(k + tg + 4) * 132 + c0];
            }
            #pragma unroll
            for (int mt = 0; mt < 4; mt++)
                #pragma unroll
                for (int nt = 0; nt < 4; nt++)
                    mma8(acc[mt][nt], af[mt], bf[nt]);
        }
        __syncthreads();
    }

    #pragma unroll
    for (int mt = 0; mt < 4; mt++) {
        #pragma unroll
        for (int nt = 0; nt < 4; nt++) {
            int row = bm + wm * 64 + mt * 16 + g;
            int col = bn + wn * 32 + nt * 8 + tg * 2;
            float b0 = bo[col], b1 = bo[col + 1];
            #pragma unroll
            for (int hf = 0; hf < 2; hf++) {
                int m = row + hf * 8;
                float2 val = make_float2(acc[mt][nt][hf * 2 + 0] + b0,
                                         acc[mt][nt][hf * 2 + 1] + b1);
                *(float2*)&g_proj[(size_t)m * NC + col] = val;
            }
        }
    }
}

// =====================================================================
// Kernel 4: LayerNorm.
// =====================================================================
__global__ __launch_bounds__(256) void ln_kernel(
    const float* __restrict__ gamma, const float* __restrict__ beta,
    float* __restrict__ out)
{
    __shared__ float redS[8];
    __shared__ float redQ[8];
    const int tid = threadIdx.x;
    const float* p = g_proj + (size_t)blockIdx.x * NC;

    float4 v = ((const float4*)p)[tid];
    float s  = v.x + v.y + v.z + v.w;
    float ss = v.x * v.x + v.y * v.y + v.z * v.z + v.w * v.w;
    #pragma unroll
    for (int o = 16; o > 0; o >>= 1) {
        s  += __shfl_xor_sync(0xffffffffu, s,  o);
        ss += __shfl_xor_sync(0xffffffffu, ss, o);
    }
    if ((tid & 31) == 0) { redS[tid >> 5] = s; redQ[tid >> 5] = ss; }
    __syncthreads();
    float S = 0.f, Q = 0.f;
    #pragma unroll
    for (int w = 0; w < 8; w++) { S += redS[w]; Q += redQ[w]; }

    float mu  = S * (1.0f / 1024.0f);
    float var = Q * (1.0f / 1024.0f) - mu * mu;
    var = fmaxf(var, 0.0f);
    float rstd = rsqrtf(var + 1e-5f);

    float4 gv = ((const float4*)gamma)[tid];
    float4 bv = ((const float4*)beta)[tid];
    float4 o;
    o.x = (v.x - mu) * rstd * gv.x + bv.x;
    o.y = (v.y - mu) * rstd * gv.y + bv.y;
    o.z = (v.z - mu) * rstd * gv.z + bv.z;
    o.w = (v.w - mu) * rstd * gv.w + bv.w;
    ((float4*)(out + (size_t)blockIdx.x * NC))[tid] = o;
}

// =====================================================================
extern "C" void kernel_launch(void* const* d_in, const int* in_sizes, int n_in,
                              void* d_out, int out_size)
{
    const float* x    = (const float*)d_in[0];
    const int*   mask = (const int*)  d_in[1];
    const float* Wq   = (const float*)d_in[2];
    const float* bq   = (const float*)d_in[3];
    const float* Wk   = (const float*)d_in[4];
    const float* bk   = (const float*)d_in[5];
    const float* Wv   = (const float*)d_in[6];
    const float* bv   = (const float*)d_in[7];
    const float* Wo   = (const float*)d_in[8];
    const float* bo   = (const float*)d_in[9];
    const float* lg   = (const float*)d_in[10];
    const float* lb   = (const float*)d_in[11];
    float* out = (float*)d_out;

    // Qs/Ks/Vs: 3*128*68*4  +  Ps: 128*132*4  +  mask: 128*4
    const int FLASH_SMEM = 3 * 128 * 68 * 4 + 128 * 132 * 4 + 128 * 4;
    cudaFuncSetAttribute(flash_kernel,
                         cudaFuncAttributeMaxDynamicSharedMemorySize, FLASH_SMEM);

    qkv_kernel  <<<dim3(8, 32, 3), 256>>>(x, Wq, bq, Wk, bk, Wv, bv);
    flash_kernel<<<dim3(8, 64), 256, FLASH_SMEM>>>(mask);
    proj_kernel <<<dim3(8, 32), 256>>>(Wo, bo);
    ln_kernel   <<<4096, 256>>>(lg, lb, out);
}